// round 9
// baseline (speedup 1.0000x reference)
#include <cuda_runtime.h>

#define IN_F 8192
#define OUT_F 8192
#define THRESH_F 50.0f
#define ROWS_PER_BLOCK 8
#define THREADS 256
#define MV_BLOCKS 512
#define ROW_GROUPS 2                          // 512 * 2 * 8 = 8192 rows
#define N_GROUPS (MV_BLOCKS * ROW_GROUPS)     // 1024 partials
#define EPI_BLOCKS 32                         // last 32 arrivals do epilogue
#define EPI_ROWS (OUT_F / EPI_BLOCKS)         // 256 rows per epilogue block

// Scratch (no allocations allowed). g_done is a MONOTONIC arrival counter:
// each launch adds exactly MV_BLOCKS, so base = old & ~(MV_BLOCKS-1) is
// race-free across CUDA-graph replays (2^32 divisible by 512).
__device__ float g_current[OUT_F];
__device__ __align__(16) float g_partial[N_GROUPS];
__device__ unsigned int g_done = 0;

__global__ void __launch_bounds__(THREADS) snn_fused_kernel(
    const float* __restrict__ spike_input,   // [IN_F]
    const float* __restrict__ syn,           // [OUT_F, IN_F] row-major
    const float* __restrict__ v_mem,         // [OUT_F]
    const float* __restrict__ v_th,          // [OUT_F]
    const float* __restrict__ noise,         // [OUT_F]
    float* __restrict__ out)                 // [spikes | v_mem_new | v_th_new]
{
    __shared__ float4 s_spike[IN_F / 4];     // 32 KB
    __shared__ float  s_spk[ROWS_PER_BLOCK];
    __shared__ float  s_red[THREADS / 32];
    __shared__ int    s_rank;                // arrival rank within this launch

    const int tid = threadIdx.x;

    // Stage spike vector into shared (reused by all 16 rows in this block).
    const float4* sp4 = reinterpret_cast<const float4*>(spike_input);
    #pragma unroll
    for (int i = 0; i < (IN_F / 4) / THREADS; i++) {
        s_spike[tid + i * THREADS] = sp4[tid + i * THREADS];
    }
    __syncthreads();

    const int warp = tid >> 5;
    const int lane = tid & 31;

    #pragma unroll
    for (int g = 0; g < ROW_GROUPS; g++) {
        const int group = blockIdx.x + g * MV_BLOCKS;
        const int row   = group * ROWS_PER_BLOCK + warp;

        const float4* r4 = reinterpret_cast<const float4*>(syn + (size_t)row * IN_F);

        float acc0 = 0.0f, acc1 = 0.0f;
        // Proven R2/R4 body: 64 float4 per lane; 2 per iter, predicated adds.
        #pragma unroll 8
        for (int it = 0; it < (IN_F / 8) / 32; it++) {
            const int i0 = (it * 2 + 0) * 32 + lane;
            const int i1 = (it * 2 + 1) * 32 + lane;
            const float4 w0 = r4[i0];
            const float4 w1 = r4[i1];
            const float4 s0 = s_spike[i0];
            const float4 s1 = s_spike[i1];
            if (w0.x > THRESH_F) acc0 += s0.x;
            if (w0.y > THRESH_F) acc1 += s0.y;
            if (w0.z > THRESH_F) acc0 += s0.z;
            if (w0.w > THRESH_F) acc1 += s0.w;
            if (w1.x > THRESH_F) acc0 += s1.x;
            if (w1.y > THRESH_F) acc1 += s1.y;
            if (w1.z > THRESH_F) acc0 += s1.z;
            if (w1.w > THRESH_F) acc1 += s1.w;
        }
        float acc = acc0 + acc1;

        #pragma unroll
        for (int o = 16; o > 0; o >>= 1) {
            acc += __shfl_xor_sync(0xFFFFFFFFu, acc, o);
        }

        if (lane == 0) {
            g_current[row] = acc;
            const float pot = v_mem[row] + acc + noise[row];
            const float spk = (pot >= v_th[row]) ? 1.0f : 0.0f;
            out[row] = spk;
            s_spk[warp] = spk;
        }
        __syncthreads();

        if (tid == 0) {
            float p = 0.0f;
            #pragma unroll
            for (int w = 0; w < ROWS_PER_BLOCK; w++) p += s_spk[w];
            g_partial[group] = p;
        }
        if (g + 1 < ROW_GROUPS) __syncthreads();
    }

    // ---- Arrival ticket; all but the last EPI_BLOCKS arrivals exit ----
    unsigned target = 0;
    if (tid == 0) {
        __threadfence();   // partials + row results visible before arrival
        const unsigned old = atomicAdd(&g_done, 1u);
        const unsigned base = old & ~(unsigned)(MV_BLOCKS - 1);
        s_rank = (int)(old - base);
        target = base + MV_BLOCKS;
    }
    __syncthreads();

    const int rank = s_rank;
    if (rank < MV_BLOCKS - EPI_BLOCKS) return;   // early blocks: done

    // ---- Last 32 arrivals: brief backoff-spin, then distributed epilogue ----
    if (tid == 0) {
        volatile unsigned* vd = &g_done;
        while ((int)(*vd - target) < 0) { __nanosleep(64); }
        __threadfence();   // acquire: order spin-read before epilogue loads
    }
    __syncthreads();

    // Inhibition: each epilogue block sums all 1024 L2-hot partials
    // (exact integer sums). 256 threads x 1 float4 each.
    {
        const float4 p = __ldcg(reinterpret_cast<const float4*>(g_partial) + tid);
        float local = (p.x + p.y) + (p.z + p.w);
        #pragma unroll
        for (int o = 16; o > 0; o >>= 1) {
            local += __shfl_xor_sync(0xFFFFFFFFu, local, o);
        }
        if (lane == 0) s_red[warp] = local;
    }
    __syncthreads();

    float total = s_red[0];
    #pragma unroll
    for (int w = 1; w < THREADS / 32; w++) total += s_red[w];
    const float inhibition = total * 0.5f;

    // Slice by arrival rank: 256 rows, one per thread. Cross-block data via
    // __ldcg (L2) to avoid stale-L1 hazards.
    const int slice = rank - (MV_BLOCKS - EPI_BLOCKS);   // 0..31
    const int r = slice * EPI_ROWS + tid;

    const float s   = __ldcg(out + r);
    const float cur = __ldcg(g_current + r);
    const float vm  = v_mem[r];
    const float vt0 = v_th[r];

    const float v_new = (vm - inhibition + cur) * (1.0f - s) * 0.5f;

    float vt = vt0 + (s - 0.1f) * 0.01f;
    vt = fminf(fmaxf(vt, 0.2f), 5.0f);

    out[OUT_F + r]     = v_new;
    out[2 * OUT_F + r] = vt;
}

extern "C" void kernel_launch(void* const* d_in, const int* in_sizes, int n_in,
                              void* d_out, int out_size)
{
    const float* spike_input = (const float*)d_in[0];   // [1, 8192]
    const float* syn         = (const float*)d_in[1];   // [8192, 8192]
    const float* v_mem       = (const float*)d_in[2];   // [8192]
    const float* v_th        = (const float*)d_in[3];   // [8192]
    const float* noise       = (const float*)d_in[4];   // [8192]
    float* out = (float*)d_out;                          // 3 * 8192 floats

    snn_fused_kernel<<<MV_BLOCKS, THREADS>>>(
        spike_input, syn, v_mem, v_th, noise, out);
}

// round 10
// speedup vs baseline: 1.2573x; 1.2573x over previous
#include <cuda_runtime.h>

#define IN_F 8192
#define OUT_F 8192
#define THRESH_F 50.0f
#define ROWS_PER_BLOCK 8
#define THREADS 256
#define MV_BLOCKS 512
#define ROW_GROUPS 2                          // 512 * 2 * 8 = 8192 rows
#define N_GROUPS (MV_BLOCKS * ROW_GROUPS)     // 1024 partials
#define EPI_BLOCKS 64                         // last 64 arrivals do epilogue
#define EPI_ROWS (OUT_F / EPI_BLOCKS)         // 128 rows per epilogue block

// Scratch (no allocations allowed). g_done is a MONOTONIC arrival counter:
// each launch adds exactly MV_BLOCKS (512), and 2^32 % 512 == 0, so
// base = old & ~511 is race-free across CUDA-graph replays.
__device__ float g_current[OUT_F];
__device__ __align__(16) float g_partial[N_GROUPS];
__device__ unsigned int g_done = 0;

// Fused kernel. __launch_bounds__(256,4) => 64-reg schedule: measured
// load-bearing for main-loop DRAM throughput (R8 fast / R9 slow at 40 regs).
__global__ void __launch_bounds__(THREADS, 4) snn_fused_kernel(
    const float* __restrict__ spike_input,   // [IN_F]
    const float* __restrict__ syn,           // [OUT_F, IN_F] row-major
    const float* __restrict__ v_mem,         // [OUT_F]
    const float* __restrict__ v_th,          // [OUT_F]
    const float* __restrict__ noise,         // [OUT_F]
    float* __restrict__ out)                 // [spikes | v_mem_new | v_th_new]
{
    __shared__ float4 s_spike[IN_F / 4];     // 32 KB
    __shared__ float  s_spk[ROWS_PER_BLOCK];
    __shared__ float  s_red[THREADS / 32];
    __shared__ int    s_rank;

    const int tid = threadIdx.x;

    // Stage spike vector into shared (reused by all 16 rows in this block).
    const float4* sp4 = reinterpret_cast<const float4*>(spike_input);
    #pragma unroll
    for (int i = 0; i < (IN_F / 4) / THREADS; i++) {
        s_spike[tid + i * THREADS] = sp4[tid + i * THREADS];
    }
    __syncthreads();

    const int warp = tid >> 5;
    const int lane = tid & 31;

    #pragma unroll
    for (int g = 0; g < ROW_GROUPS; g++) {
        const int group = blockIdx.x + g * MV_BLOCKS;
        const int row   = group * ROWS_PER_BLOCK + warp;

        const float4* r4 = reinterpret_cast<const float4*>(syn + (size_t)row * IN_F);

        float acc0 = 0.0f, acc1 = 0.0f;
        // Proven R2/R4/R8 body: 64 float4 per lane; 2 per iter, predicated.
        #pragma unroll 8
        for (int it = 0; it < (IN_F / 8) / 32; it++) {
            const int i0 = (it * 2 + 0) * 32 + lane;
            const int i1 = (it * 2 + 1) * 32 + lane;
            const float4 w0 = r4[i0];
            const float4 w1 = r4[i1];
            const float4 s0 = s_spike[i0];
            const float4 s1 = s_spike[i1];
            if (w0.x > THRESH_F) acc0 += s0.x;
            if (w0.y > THRESH_F) acc1 += s0.y;
            if (w0.z > THRESH_F) acc0 += s0.z;
            if (w0.w > THRESH_F) acc1 += s0.w;
            if (w1.x > THRESH_F) acc0 += s1.x;
            if (w1.y > THRESH_F) acc1 += s1.y;
            if (w1.z > THRESH_F) acc0 += s1.z;
            if (w1.w > THRESH_F) acc1 += s1.w;
        }
        float acc = acc0 + acc1;

        #pragma unroll
        for (int o = 16; o > 0; o >>= 1) {
            acc += __shfl_xor_sync(0xFFFFFFFFu, acc, o);
        }

        if (lane == 0) {
            g_current[row] = acc;
            const float pot = v_mem[row] + acc + noise[row];
            const float spk = (pot >= v_th[row]) ? 1.0f : 0.0f;
            out[row] = spk;
            // v_th_new is row-local: write it here, off the dependent tail.
            float vt = v_th[row] + (spk - 0.1f) * 0.01f;
            out[2 * OUT_F + row] = fminf(fmaxf(vt, 0.2f), 5.0f);
            s_spk[warp] = spk;
        }
        __syncthreads();

        if (tid == 0) {
            float p = 0.0f;
            #pragma unroll
            for (int w = 0; w < ROWS_PER_BLOCK; w++) p += s_spk[w];
            g_partial[group] = p;
        }
        if (g + 1 < ROW_GROUPS) __syncthreads();
    }

    // ---- Arrival ticket; all but the last EPI_BLOCKS arrivals exit ----
    unsigned target = 0;
    if (tid == 0) {
        __threadfence();   // partials + g_current visible before arrival
        const unsigned old = atomicAdd(&g_done, 1u);
        const unsigned base = old & ~(unsigned)(MV_BLOCKS - 1);
        s_rank = (int)(old - base);
        target = base + MV_BLOCKS;
    }
    __syncthreads();

    const int rank = s_rank;
    if (rank < MV_BLOCKS - EPI_BLOCKS) return;   // early blocks: done

    // ---- Last 64 arrivals: backoff-spin, then v_mem epilogue ----
    if (tid == 0) {
        volatile unsigned* vd = &g_done;
        while ((int)(*vd - target) < 0) { __nanosleep(32); }
        __threadfence();   // acquire: order spin-read before epilogue loads
    }
    __syncthreads();

    // Inhibition: sum all 1024 L2-hot partials (exact integer sums).
    {
        const float4 p = __ldcg(reinterpret_cast<const float4*>(g_partial) + tid);
        float local = (p.x + p.y) + (p.z + p.w);
        #pragma unroll
        for (int o = 16; o > 0; o >>= 1) {
            local += __shfl_xor_sync(0xFFFFFFFFu, local, o);
        }
        if (lane == 0) s_red[warp] = local;
    }
    __syncthreads();

    float total = s_red[0];
    #pragma unroll
    for (int w = 1; w < THREADS / 32; w++) total += s_red[w];
    const float inhibition = total * 0.5f;

    // v_mem_new for this block's 128 rows (tid < 128). Spike recomputed from
    // inputs + g_current with the IDENTICAL comparison (bit-exact), avoiding
    // a dependent reload of out[]. g_current via __ldcg (cross-block data).
    if (tid < EPI_ROWS) {
        const int slice = rank - (MV_BLOCKS - EPI_BLOCKS);   // 0..63
        const int r = slice * EPI_ROWS + tid;

        const float cur = __ldcg(g_current + r);
        const float vm  = v_mem[r];
        const float s   = ((vm + cur + noise[r]) >= v_th[r]) ? 1.0f : 0.0f;

        out[OUT_F + r] = (vm - inhibition + cur) * (1.0f - s) * 0.5f;
    }
}

extern "C" void kernel_launch(void* const* d_in, const int* in_sizes, int n_in,
                              void* d_out, int out_size)
{
    const float* spike_input = (const float*)d_in[0];   // [1, 8192]
    const float* syn         = (const float*)d_in[1];   // [8192, 8192]
    const float* v_mem       = (const float*)d_in[2];   // [8192]
    const float* v_th        = (const float*)d_in[3];   // [8192]
    const float* noise       = (const float*)d_in[4];   // [8192]
    float* out = (float*)d_out;                          // 3 * 8192 floats

    snn_fused_kernel<<<MV_BLOCKS, THREADS>>>(
        spike_input, syn, v_mem, v_th, noise, out);
}